// round 13
// baseline (speedup 1.0000x reference)
#include <cuda_runtime.h>
#include <cuda_fp16.h>
#include <math.h>

// ============================================================================
// PermInvariantQNN — piecewise-linear collapse of the scalar encoder.
// Round 13: direct uniform interpolation table (2048 cells x 5 moments,
//           slope+center-value in half2). No index table, no walk, no probes:
//           eval = clamp + LDS.128 + LDS.32 + 5 FMA. Prep simplified.
// ============================================================================

#define BATCH     131072
#define NG        2048
#define XLO_F     (-6.0f)
#define STEP_F    (12.0f / 2048.0f)
#define INVSTEP_F (2048.0f / 12.0f)
#define UOFF_F    1024.0f

// cell c: A = {h2(s0,v0), h2(s1,v1), h2(s2,v2), h2(s3,v3)}, B = h2(s4,v4)
// slopes/values pre-scaled by 1/64; v = f(center_c) exact, s = slope of the
// segment containing center_c.
__device__ uint4        g_A[NG];
__device__ unsigned int g_B[NG];

// ----------------------------------------------------------------------------
// Prep: 1 block x 512 threads. Breakpoints -> sort -> per-segment affine
// coefficients -> per-cell table.
// ----------------------------------------------------------------------------
__global__ void prep_kernel(const float* __restrict__ eW1, const float* __restrict__ eb1,
                            const float* __restrict__ eW2, const float* __restrict__ eb2,
                            const float* __restrict__ eW3, const float* __restrict__ eb3)
{
    __shared__ float sa[20], sb1[20], sW2[400], sb2[20], sW3[100], sb3[5];
    __shared__ float s_t[21];
    __shared__ int   s_n1, s_n;
    __shared__ float cand[512];
    __shared__ float seg_s[512 * 5];             // 10 KB
    __shared__ float seg_c[512 * 5];             // 10 KB

    const int tid = threadIdx.x;

    if (tid < 20)  { sa[tid] = eW1[tid]; sb1[tid] = eb1[tid]; sb2[tid] = eb2[tid]; }
    if (tid < 400) sW2[tid] = eW2[tid];
    if (tid < 100) sW3[tid] = eW3[tid];
    if (tid < 5)   sb3[tid] = eb3[tid];
    cand[tid] = INFINITY;
    if (tid == 0) s_n = 0;
    __syncthreads();

    // ---- phase 1: layer-1 breakpoints via warp rank-sort ----
    if (tid < 32) {
        float tj = INFINITY;
        if (tid < 20) {
            float a = sa[tid];
            if (a != 0.0f) {
                float t = -sb1[tid] / a;
                if (isfinite(t)) tj = t;
            }
        }
        int rnk = 0;
        #pragma unroll
        for (int j = 0; j < 32; j++) {
            float u = __shfl_sync(0xFFFFFFFFu, tj, j);
            rnk += (u < tj) || (u == tj && j < tid);
        }
        bool fin = isfinite(tj);
        if (fin) { s_t[rnk] = tj; cand[rnk] = tj; }
        unsigned m = __ballot_sync(0xFFFFFFFFu, fin);
        if (tid == 0) { s_n1 = __popc(m); atomicAdd(&s_n, __popc(m)); }
    }
    __syncthreads();
    const int n1 = s_n1;

    // ---- phase 2: layer-2 zero crossings ----
    if (tid < 21 * 20) {
        int p = tid / 20, k = tid % 20;
        if (p <= n1) {
            float lo = (p == 0)  ? -INFINITY : s_t[p - 1];
            float hi = (p == n1) ?  INFINITY : s_t[p];
            float xr;
            if (n1 == 0)      xr = 0.0f;
            else if (p == 0)  xr = s_t[0] - 1.0f;
            else if (p == n1) xr = s_t[n1 - 1] + 1.0f;
            else              xr = 0.5f * (lo + hi);
            float zs = 0.0f, zi = sb2[k];
            for (int j = 0; j < 20; j++) {
                float pre = fmaf(sa[j], xr, sb1[j]);
                if (pre > 0.0f) {
                    zs = fmaf(sa[j],  sW2[j * 20 + k], zs);
                    zi = fmaf(sb1[j], sW2[j * 20 + k], zi);
                }
            }
            if (zs != 0.0f) {
                float xc = -zi / zs;
                if (isfinite(xc) && xc > lo && xc < hi) {
                    cand[20 + p * 20 + k] = xc;
                    atomicAdd(&s_n, 1);
                }
            }
        }
    }
    __syncthreads();

    // ---- phase 3: hybrid bitonic sort ----
    {
        float v = cand[tid];
        for (int k = 2; k <= 512; k <<= 1) {
            for (int j = k >> 1; j > 0; j >>= 1) {
                float u;
                if (j >= 32) {
                    cand[tid] = v; __syncthreads();
                    u = cand[tid ^ j]; __syncthreads();
                } else {
                    u = __shfl_xor_sync(0xFFFFFFFFu, v, j);
                }
                bool up = ((tid & k) == 0);
                bool keepmin = (up == ((tid & j) == 0));
                v = keepmin ? fminf(v, u) : fmaxf(v, u);
            }
        }
        cand[tid] = v;
        __syncthreads();
    }
    const int n = s_n;

    // ---- phase 4: per-segment affine coefficients (threads 0..n) ----
    if (tid <= n) {
        float xr;
        if (n == 0)        xr = 0.0f;
        else if (tid == 0) xr = cand[0] - 1.0f;
        else if (tid == n) xr = cand[n - 1] + 1.0f;
        else               xr = 0.5f * (cand[tid - 1] + cand[tid]);

        float ha[20], hb[20];
        #pragma unroll
        for (int j = 0; j < 20; j++) {
            float pre = fmaf(sa[j], xr, sb1[j]);
            bool act = pre > 0.0f;
            ha[j] = act ? sa[j]  : 0.0f;
            hb[j] = act ? sb1[j] : 0.0f;
        }
        float sm[5] = {0, 0, 0, 0, 0}, cm[5] = {0, 0, 0, 0, 0};
        for (int k = 0; k < 20; k++) {
            float zs = 0.0f, zi = sb2[k];
            #pragma unroll
            for (int j = 0; j < 20; j++) {
                zs = fmaf(ha[j], sW2[j * 20 + k], zs);
                zi = fmaf(hb[j], sW2[j * 20 + k], zi);
            }
            if (fmaf(zs, xr, zi) > 0.0f) {
                #pragma unroll
                for (int m = 0; m < 5; m++) {
                    sm[m] = fmaf(zs, sW3[k * 5 + m], sm[m]);
                    cm[m] = fmaf(zi, sW3[k * 5 + m], cm[m]);
                }
            }
        }
        #pragma unroll
        for (int m = 0; m < 5; m++) {
            seg_s[tid * 5 + m] = sm[m];
            seg_c[tid * 5 + m] = cm[m] + sb3[m];
        }
    }
    __syncthreads();

    // ---- phase 5: per-cell table (4 cells/thread) ----
    for (int c = tid; c < NG; c += 512) {
        float center = XLO_F + ((float)c + 0.5f) * STEP_F;
        int lo = 0, hi = n;
        while (lo < hi) {
            int mid = (lo + hi) >> 1;
            if (cand[mid] <= center) lo = mid + 1; else hi = mid;
        }
        const int s = lo;                        // segment containing center
        unsigned p[5];
        #pragma unroll
        for (int m = 0; m < 5; m++) {
            float sl = seg_s[s * 5 + m];
            float v  = fmaf(sl, center, seg_c[s * 5 + m]);
            __half2 h = __floats2half2_rn(sl * 0.015625f, v * 0.015625f);
            p[m] = *(unsigned*)&h;
        }
        g_A[c] = make_uint4(p[0], p[1], p[2], p[3]);
        g_B[c] = p[4];
    }
}

// ----------------------------------------------------------------------------
// Fused encoder+decoder: thread-pair per row.
// ----------------------------------------------------------------------------
__device__ __forceinline__ void pwl_eval(float x,
                                         const uint4* __restrict__ sA,
                                         const unsigned* __restrict__ sB,
                                         float acc[5])
{
    float u = fmaf(x, INVSTEP_F, UOFF_F);
    int c = __float2int_rz(u);
    c = min(max(c, 0), NG - 1);
    float dx = x - fmaf((float)c + 0.5f, STEP_F, XLO_F);
    uint4    A = sA[c];
    unsigned B = sB[c];
    float2 m0 = __half22float2(*(__half2*)&A.x);
    float2 m1 = __half22float2(*(__half2*)&A.y);
    float2 m2 = __half22float2(*(__half2*)&A.z);
    float2 m3 = __half22float2(*(__half2*)&A.w);
    float2 m4 = __half22float2(*(__half2*)&B);
    acc[0] += fmaf(m0.x, dx, m0.y);
    acc[1] += fmaf(m1.x, dx, m1.y);
    acc[2] += fmaf(m2.x, dx, m2.y);
    acc[3] += fmaf(m3.x, dx, m3.y);
    acc[4] += fmaf(m4.x, dx, m4.y);
}

__global__ __launch_bounds__(256, 5) void fused_kernel(
    const float* __restrict__ inv,  const float* __restrict__ noninv,
    const float* __restrict__ dW1,  const float* __restrict__ db1,
    const float* __restrict__ dW2,  const float* __restrict__ db2,
    const float* __restrict__ dW3,  const float* __restrict__ db3,
    float* __restrict__ out)
{
    __shared__ __align__(16) uint4        s_A[NG];   // 32 KB
    __shared__ __align__(16) unsigned int s_B[NG];   // 8 KB
    __shared__ __align__(16) float        s_dw[784]; // 3.1 KB

    const int tid = threadIdx.x;

    {
        #pragma unroll
        for (int i = tid; i < NG; i += 256) s_A[i] = g_A[i];
        uint4* bdst = (uint4*)s_B;
        const uint4* bsrc = (const uint4*)g_B;
        #pragma unroll
        for (int i = tid; i < NG / 4; i += 256) bdst[i] = bsrc[i];
        for (int i = tid; i < 260; i += 256) s_dw[i] = dW1[i];
        if (tid < 20) s_dw[260 + tid] = db1[tid];
        for (int i = tid; i < 400; i += 256) s_dw[280 + i] = dW2[i];
        if (tid < 20) s_dw[680 + tid] = db2[tid];
        if (tid < 80) s_dw[700 + tid] = dW3[tid];
        if (tid < 4)  s_dw[780 + tid] = db3[tid];
    }
    __syncthreads();

    const int gtid = blockIdx.x * 256 + tid;
    const int r    = gtid >> 1;          // row
    const int half = gtid & 1;           // 0/1: input half + neuron half
    const int nb   = half * 10;          // neuron base

    // -------- encoder: my 32 of the row's 64 inputs --------
    float acc[5] = {0, 0, 0, 0, 0};
    const float4* p0 = (const float4*)inv + (size_t)r * 16 + half * 8;
    #pragma unroll
    for (int i = 0; i < 8; i++) {
        float4 a = p0[i];
        pwl_eval(a.x, s_A, s_B, acc);
        pwl_eval(a.y, s_A, s_B, acc);
        pwl_eval(a.z, s_A, s_B, acc);
        pwl_eval(a.w, s_A, s_B, acc);
    }

    // -------- combine moments across the pair; build cat[13] --------
    float cat[13];
    #pragma unroll
    for (int m = 0; m < 5; m++)
        cat[m] = acc[m] + __shfl_xor_sync(0xFFFFFFFFu, acc[m], 1);
    {
        float4 u0 = *(const float4*)(noninv + (size_t)r * 8);
        float4 u1 = *(const float4*)(noninv + (size_t)r * 8 + 4);
        cat[5] = u0.x; cat[6] = u0.y; cat[7]  = u0.z; cat[8]  = u0.w;
        cat[9] = u1.x; cat[10] = u1.y; cat[11] = u1.z; cat[12] = u1.w;
    }

    // -------- decoder layer 1: my 10 neurons --------
    float myh[10];
    #pragma unroll
    for (int i = 0; i < 10; i += 2) {
        float2 z = *(const float2*)&s_dw[260 + nb + i];
        #pragma unroll
        for (int c = 0; c < 13; c++) {
            float2 w = *(const float2*)&s_dw[c * 20 + nb + i];
            z.x = fmaf(cat[c], w.x, z.x);
            z.y = fmaf(cat[c], w.y, z.y);
        }
        myh[i]     = fmaxf(z.x, 0.0f);
        myh[i + 1] = fmaxf(z.y, 0.0f);
    }

    // -------- exchange h halves --------
    float hall[20];
    #pragma unroll
    for (int i = 0; i < 10; i++) {
        float o = __shfl_xor_sync(0xFFFFFFFFu, myh[i], 1);
        hall[i]      = half ? o      : myh[i];
        hall[10 + i] = half ? myh[i] : o;
    }

    // -------- decoder layer 2: my 10 neurons --------
    float g[10];
    #pragma unroll
    for (int i = 0; i < 10; i += 2) {
        float2 z = *(const float2*)&s_dw[680 + nb + i];
        #pragma unroll
        for (int j = 0; j < 20; j++) {
            float2 w = *(const float2*)&s_dw[280 + j * 20 + nb + i];
            z.x = fmaf(hall[j], w.x, z.x);
            z.y = fmaf(hall[j], w.y, z.y);
        }
        g[i]     = fmaxf(z.x, 0.0f);
        g[i + 1] = fmaxf(z.y, 0.0f);
    }

    // -------- decoder layer 3: partial + shfl reduce --------
    float4 o = half ? make_float4(0.f, 0.f, 0.f, 0.f)
                    : *(const float4*)&s_dw[780];
    #pragma unroll
    for (int i = 0; i < 10; i++) {
        float4 w = *(const float4*)&s_dw[700 + (nb + i) * 4];
        o.x = fmaf(g[i], w.x, o.x);
        o.y = fmaf(g[i], w.y, o.y);
        o.z = fmaf(g[i], w.z, o.z);
        o.w = fmaf(g[i], w.w, o.w);
    }
    o.x += __shfl_xor_sync(0xFFFFFFFFu, o.x, 1);
    o.y += __shfl_xor_sync(0xFFFFFFFFu, o.y, 1);
    o.z += __shfl_xor_sync(0xFFFFFFFFu, o.z, 1);
    o.w += __shfl_xor_sync(0xFFFFFFFFu, o.w, 1);
    if (half == 0)
        *(float4*)(out + (size_t)r * 4) = o;
}

// ----------------------------------------------------------------------------
extern "C" void kernel_launch(void* const* d_in, const int* in_sizes, int n_in,
                              void* d_out, int out_size)
{
    (void)in_sizes; (void)n_in; (void)out_size;
    const float* invar  = (const float*)d_in[0];
    const float* noninv = (const float*)d_in[1];
    const float* eW1 = (const float*)d_in[2];
    const float* eb1 = (const float*)d_in[3];
    const float* eW2 = (const float*)d_in[4];
    const float* eb2 = (const float*)d_in[5];
    const float* eW3 = (const float*)d_in[6];
    const float* eb3 = (const float*)d_in[7];
    const float* dW1 = (const float*)d_in[8];
    const float* db1 = (const float*)d_in[9];
    const float* dW2 = (const float*)d_in[10];
    const float* db2 = (const float*)d_in[11];
    const float* dW3 = (const float*)d_in[12];
    const float* db3 = (const float*)d_in[13];

    prep_kernel<<<1, 512>>>(eW1, eb1, eW2, eb2, eW3, eb3);
    fused_kernel<<<BATCH / 128, 256>>>(invar, noninv,
                                       dW1, db1, dW2, db2, dW3, db3,
                                       (float*)d_out);
}

// round 14
// speedup vs baseline: 1.5846x; 1.5846x over previous
#include <cuda_runtime.h>
#include <cuda_fp16.h>
#include <math.h>

// ============================================================================
// PermInvariantQNN — piecewise-linear collapse of the scalar encoder.
// Round 14: direct uniform table (NG=1024), 24B/cell stride-6 records read as
//           2xLDS.64 + 1xLDS.32 (R9's proven conflict shape), no find/walk.
// ============================================================================

#define BATCH     131072
#define NG        1024
#define XLO_F     (-6.0f)
#define STEP_F    (12.0f / 1024.0f)
#define INVSTEP_F (1024.0f / 12.0f)
#define UOFF_F    512.0f

// cell c (6 words @ c*6): [h2(s0,v0), h2(s1,v1), h2(s2,v2), h2(s3,v3),
//                          h2(s4,v4), pad].  s,v scaled by 1/64; v exact at
//                          cell center, s = slope of segment containing center.
__device__ unsigned int g_tab[NG * 6];

// ----------------------------------------------------------------------------
// Prep: 1 block x 512 threads.
// ----------------------------------------------------------------------------
__global__ void prep_kernel(const float* __restrict__ eW1, const float* __restrict__ eb1,
                            const float* __restrict__ eW2, const float* __restrict__ eb2,
                            const float* __restrict__ eW3, const float* __restrict__ eb3)
{
    __shared__ float sa[20], sb1[20], sW2[400], sb2[20], sW3[100], sb3[5];
    __shared__ float s_t[21];
    __shared__ int   s_n1, s_n;
    __shared__ float cand[512];
    __shared__ float seg_s[512 * 5];
    __shared__ float seg_c[512 * 5];

    const int tid = threadIdx.x;

    if (tid < 20)  { sa[tid] = eW1[tid]; sb1[tid] = eb1[tid]; sb2[tid] = eb2[tid]; }
    if (tid < 400) sW2[tid] = eW2[tid];
    if (tid < 100) sW3[tid] = eW3[tid];
    if (tid < 5)   sb3[tid] = eb3[tid];
    cand[tid] = INFINITY;
    if (tid == 0) s_n = 0;
    __syncthreads();

    // ---- phase 1: layer-1 breakpoints via warp rank-sort ----
    if (tid < 32) {
        float tj = INFINITY;
        if (tid < 20) {
            float a = sa[tid];
            if (a != 0.0f) {
                float t = -sb1[tid] / a;
                if (isfinite(t)) tj = t;
            }
        }
        int rnk = 0;
        #pragma unroll
        for (int j = 0; j < 32; j++) {
            float u = __shfl_sync(0xFFFFFFFFu, tj, j);
            rnk += (u < tj) || (u == tj && j < tid);
        }
        bool fin = isfinite(tj);
        if (fin) { s_t[rnk] = tj; cand[rnk] = tj; }
        unsigned m = __ballot_sync(0xFFFFFFFFu, fin);
        if (tid == 0) { s_n1 = __popc(m); atomicAdd(&s_n, __popc(m)); }
    }
    __syncthreads();
    const int n1 = s_n1;

    // ---- phase 2: layer-2 zero crossings ----
    if (tid < 21 * 20) {
        int p = tid / 20, k = tid % 20;
        if (p <= n1) {
            float lo = (p == 0)  ? -INFINITY : s_t[p - 1];
            float hi = (p == n1) ?  INFINITY : s_t[p];
            float xr;
            if (n1 == 0)      xr = 0.0f;
            else if (p == 0)  xr = s_t[0] - 1.0f;
            else if (p == n1) xr = s_t[n1 - 1] + 1.0f;
            else              xr = 0.5f * (lo + hi);
            float zs = 0.0f, zi = sb2[k];
            for (int j = 0; j < 20; j++) {
                float pre = fmaf(sa[j], xr, sb1[j]);
                if (pre > 0.0f) {
                    zs = fmaf(sa[j],  sW2[j * 20 + k], zs);
                    zi = fmaf(sb1[j], sW2[j * 20 + k], zi);
                }
            }
            if (zs != 0.0f) {
                float xc = -zi / zs;
                if (isfinite(xc) && xc > lo && xc < hi) {
                    cand[20 + p * 20 + k] = xc;
                    atomicAdd(&s_n, 1);
                }
            }
        }
    }
    __syncthreads();

    // ---- phase 3: hybrid bitonic sort ----
    {
        float v = cand[tid];
        for (int k = 2; k <= 512; k <<= 1) {
            for (int j = k >> 1; j > 0; j >>= 1) {
                float u;
                if (j >= 32) {
                    cand[tid] = v; __syncthreads();
                    u = cand[tid ^ j]; __syncthreads();
                } else {
                    u = __shfl_xor_sync(0xFFFFFFFFu, v, j);
                }
                bool up = ((tid & k) == 0);
                bool keepmin = (up == ((tid & j) == 0));
                v = keepmin ? fminf(v, u) : fmaxf(v, u);
            }
        }
        cand[tid] = v;
        __syncthreads();
    }
    const int n = s_n;

    // ---- phase 4: per-segment affine coefficients (threads 0..n) ----
    if (tid <= n) {
        float xr;
        if (n == 0)        xr = 0.0f;
        else if (tid == 0) xr = cand[0] - 1.0f;
        else if (tid == n) xr = cand[n - 1] + 1.0f;
        else               xr = 0.5f * (cand[tid - 1] + cand[tid]);

        float ha[20], hb[20];
        #pragma unroll
        for (int j = 0; j < 20; j++) {
            float pre = fmaf(sa[j], xr, sb1[j]);
            bool act = pre > 0.0f;
            ha[j] = act ? sa[j]  : 0.0f;
            hb[j] = act ? sb1[j] : 0.0f;
        }
        float sm[5] = {0, 0, 0, 0, 0}, cm[5] = {0, 0, 0, 0, 0};
        for (int k = 0; k < 20; k++) {
            float zs = 0.0f, zi = sb2[k];
            #pragma unroll
            for (int j = 0; j < 20; j++) {
                zs = fmaf(ha[j], sW2[j * 20 + k], zs);
                zi = fmaf(hb[j], sW2[j * 20 + k], zi);
            }
            if (fmaf(zs, xr, zi) > 0.0f) {
                #pragma unroll
                for (int m = 0; m < 5; m++) {
                    sm[m] = fmaf(zs, sW3[k * 5 + m], sm[m]);
                    cm[m] = fmaf(zi, sW3[k * 5 + m], cm[m]);
                }
            }
        }
        #pragma unroll
        for (int m = 0; m < 5; m++) {
            seg_s[tid * 5 + m] = sm[m];
            seg_c[tid * 5 + m] = cm[m] + sb3[m];
        }
    }
    __syncthreads();

    // ---- phase 5: per-cell table (2 cells/thread) ----
    for (int c = tid; c < NG; c += 512) {
        float center = XLO_F + ((float)c + 0.5f) * STEP_F;
        int lo = 0, hi = n;
        while (lo < hi) {
            int mid = (lo + hi) >> 1;
            if (cand[mid] <= center) lo = mid + 1; else hi = mid;
        }
        const int s = lo;                        // segment containing center
        unsigned* rec = g_tab + c * 6;
        #pragma unroll
        for (int m = 0; m < 5; m++) {
            float sl = seg_s[s * 5 + m];
            float v  = fmaf(sl, center, seg_c[s * 5 + m]);
            __half2 h = __floats2half2_rn(sl * 0.015625f, v * 0.015625f);
            rec[m] = *(unsigned*)&h;
        }
        rec[5] = 0;
    }
}

// ----------------------------------------------------------------------------
// Fused encoder+decoder: thread-pair per row.
// ----------------------------------------------------------------------------
__device__ __forceinline__ void pwl_eval(float x,
                                         const unsigned* __restrict__ s_tab,
                                         float acc[5])
{
    float u = fmaf(x, INVSTEP_F, UOFF_F);
    int c = __float2int_rz(u);
    c = min(max(c, 0), NG - 1);
    float dx = x - fmaf((float)c + 0.5f, STEP_F, XLO_F);
    const uint2* p = (const uint2*)(s_tab + c * 6);  // 24B stride, 8B aligned
    uint2 ab = p[0];                                 // (m0, m1)
    uint2 cd = p[1];                                 // (m2, m3)
    unsigned e = s_tab[c * 6 + 4];                   // m4
    float2 m0 = __half22float2(*(__half2*)&ab.x);
    float2 m1 = __half22float2(*(__half2*)&ab.y);
    float2 m2 = __half22float2(*(__half2*)&cd.x);
    float2 m3 = __half22float2(*(__half2*)&cd.y);
    float2 m4 = __half22float2(*(__half2*)&e);
    acc[0] += fmaf(m0.x, dx, m0.y);
    acc[1] += fmaf(m1.x, dx, m1.y);
    acc[2] += fmaf(m2.x, dx, m2.y);
    acc[3] += fmaf(m3.x, dx, m3.y);
    acc[4] += fmaf(m4.x, dx, m4.y);
}

__global__ __launch_bounds__(256, 5) void fused_kernel(
    const float* __restrict__ inv,  const float* __restrict__ noninv,
    const float* __restrict__ dW1,  const float* __restrict__ db1,
    const float* __restrict__ dW2,  const float* __restrict__ db2,
    const float* __restrict__ dW3,  const float* __restrict__ db3,
    float* __restrict__ out)
{
    __shared__ __align__(16) unsigned int s_tab[NG * 6]; // 24 KB
    __shared__ __align__(16) float        s_dw[784];     // 3.1 KB

    const int tid = threadIdx.x;

    {
        const uint4* src = (const uint4*)g_tab;          // 1536 uint4
        uint4* dst = (uint4*)s_tab;
        #pragma unroll
        for (int i = tid; i < NG * 6 / 4; i += 256) dst[i] = src[i];
        for (int i = tid; i < 260; i += 256) s_dw[i] = dW1[i];
        if (tid < 20) s_dw[260 + tid] = db1[tid];
        for (int i = tid; i < 400; i += 256) s_dw[280 + i] = dW2[i];
        if (tid < 20) s_dw[680 + tid] = db2[tid];
        if (tid < 80) s_dw[700 + tid] = dW3[tid];
        if (tid < 4)  s_dw[780 + tid] = db3[tid];
    }
    __syncthreads();

    const int gtid = blockIdx.x * 256 + tid;
    const int r    = gtid >> 1;          // row
    const int half = gtid & 1;           // 0/1: input half + neuron half
    const int nb   = half * 10;          // neuron base

    // -------- encoder: my 32 of the row's 64 inputs --------
    float acc[5] = {0, 0, 0, 0, 0};
    const float4* p0 = (const float4*)inv + (size_t)r * 16 + half * 8;
    #pragma unroll
    for (int i = 0; i < 8; i++) {
        float4 a = p0[i];
        pwl_eval(a.x, s_tab, acc);
        pwl_eval(a.y, s_tab, acc);
        pwl_eval(a.z, s_tab, acc);
        pwl_eval(a.w, s_tab, acc);
    }

    // -------- combine moments across the pair; build cat[13] --------
    float cat[13];
    #pragma unroll
    for (int m = 0; m < 5; m++)
        cat[m] = acc[m] + __shfl_xor_sync(0xFFFFFFFFu, acc[m], 1);
    {
        float4 u0 = *(const float4*)(noninv + (size_t)r * 8);
        float4 u1 = *(const float4*)(noninv + (size_t)r * 8 + 4);
        cat[5] = u0.x; cat[6] = u0.y; cat[7]  = u0.z; cat[8]  = u0.w;
        cat[9] = u1.x; cat[10] = u1.y; cat[11] = u1.z; cat[12] = u1.w;
    }

    // -------- decoder layer 1: my 10 neurons --------
    float myh[10];
    #pragma unroll
    for (int i = 0; i < 10; i += 2) {
        float2 z = *(const float2*)&s_dw[260 + nb + i];
        #pragma unroll
        for (int c = 0; c < 13; c++) {
            float2 w = *(const float2*)&s_dw[c * 20 + nb + i];
            z.x = fmaf(cat[c], w.x, z.x);
            z.y = fmaf(cat[c], w.y, z.y);
        }
        myh[i]     = fmaxf(z.x, 0.0f);
        myh[i + 1] = fmaxf(z.y, 0.0f);
    }

    // -------- exchange h halves --------
    float hall[20];
    #pragma unroll
    for (int i = 0; i < 10; i++) {
        float o = __shfl_xor_sync(0xFFFFFFFFu, myh[i], 1);
        hall[i]      = half ? o      : myh[i];
        hall[10 + i] = half ? myh[i] : o;
    }

    // -------- decoder layer 2: my 10 neurons --------
    float g[10];
    #pragma unroll
    for (int i = 0; i < 10; i += 2) {
        float2 z = *(const float2*)&s_dw[680 + nb + i];
        #pragma unroll
        for (int j = 0; j < 20; j++) {
            float2 w = *(const float2*)&s_dw[280 + j * 20 + nb + i];
            z.x = fmaf(hall[j], w.x, z.x);
            z.y = fmaf(hall[j], w.y, z.y);
        }
        g[i]     = fmaxf(z.x, 0.0f);
        g[i + 1] = fmaxf(z.y, 0.0f);
    }

    // -------- decoder layer 3: partial + shfl reduce --------
    float4 o = half ? make_float4(0.f, 0.f, 0.f, 0.f)
                    : *(const float4*)&s_dw[780];
    #pragma unroll
    for (int i = 0; i < 10; i++) {
        float4 w = *(const float4*)&s_dw[700 + (nb + i) * 4];
        o.x = fmaf(g[i], w.x, o.x);
        o.y = fmaf(g[i], w.y, o.y);
        o.z = fmaf(g[i], w.z, o.z);
        o.w = fmaf(g[i], w.w, o.w);
    }
    o.x += __shfl_xor_sync(0xFFFFFFFFu, o.x, 1);
    o.y += __shfl_xor_sync(0xFFFFFFFFu, o.y, 1);
    o.z += __shfl_xor_sync(0xFFFFFFFFu, o.z, 1);
    o.w += __shfl_xor_sync(0xFFFFFFFFu, o.w, 1);
    if (half == 0)
        *(float4*)(out + (size_t)r * 4) = o;
}

// ----------------------------------------------------------------------------
extern "C" void kernel_launch(void* const* d_in, const int* in_sizes, int n_in,
                              void* d_out, int out_size)
{
    (void)in_sizes; (void)n_in; (void)out_size;
    const float* invar  = (const float*)d_in[0];
    const float* noninv = (const float*)d_in[1];
    const float* eW1 = (const float*)d_in[2];
    const float* eb1 = (const float*)d_in[3];
    const float* eW2 = (const float*)d_in[4];
    const float* eb2 = (const float*)d_in[5];
    const float* eW3 = (const float*)d_in[6];
    const float* eb3 = (const float*)d_in[7];
    const float* dW1 = (const float*)d_in[8];
    const float* db1 = (const float*)d_in[9];
    const float* dW2 = (const float*)d_in[10];
    const float* db2 = (const float*)d_in[11];
    const float* dW3 = (const float*)d_in[12];
    const float* db3 = (const float*)d_in[13];

    prep_kernel<<<1, 512>>>(eW1, eb1, eW2, eb2, eW3, eb3);
    fused_kernel<<<BATCH / 128, 256>>>(invar, noninv,
                                       dW1, db1, dW2, db2, dW3, db3,
                                       (float*)d_out);
}

// round 15
// speedup vs baseline: 1.6494x; 1.0409x over previous
#include <cuda_runtime.h>
#include <cuda_fp16.h>
#include <math.h>

// ============================================================================
// PermInvariantQNN — piecewise-linear collapse of the scalar encoder.
// Round 15: split-array table (AB/CD uint2 @16 classes, m4 @32 classes) to cut
//           bank conflicts; PDL overlap of prep with fused prologue.
// ============================================================================

#define BATCH     131072
#define NG        1024
#define XLO_F     (-6.0f)
#define STEP_F    (12.0f / 1024.0f)
#define INVSTEP_F (1024.0f / 12.0f)
#define UOFF_F    512.0f

// cell c: AB = (h2(s0,v0), h2(s1,v1)), CD = (h2(s2,v2), h2(s3,v3)), M4 = h2(s4,v4)
// s,v scaled by 1/64; v exact at cell center, s = slope of segment at center.
__device__ uint2        g_AB[NG];
__device__ uint2        g_CD[NG];
__device__ unsigned int g_M4[NG];

#define GRIDDEP_WAIT()   asm volatile("griddepcontrol.wait;" ::: "memory")
#define GRIDDEP_LAUNCH() asm volatile("griddepcontrol.launch_dependents;" ::: "memory")

// ----------------------------------------------------------------------------
// Prep: 1 block x 512 threads.
// ----------------------------------------------------------------------------
__global__ void prep_kernel(const float* __restrict__ eW1, const float* __restrict__ eb1,
                            const float* __restrict__ eW2, const float* __restrict__ eb2,
                            const float* __restrict__ eW3, const float* __restrict__ eb3)
{
    __shared__ float sa[20], sb1[20], sW2[400], sb2[20], sW3[100], sb3[5];
    __shared__ float s_t[21];
    __shared__ int   s_n1, s_n;
    __shared__ float cand[512];
    __shared__ float seg_s[512 * 5];
    __shared__ float seg_c[512 * 5];

    const int tid = threadIdx.x;

    if (tid < 20)  { sa[tid] = eW1[tid]; sb1[tid] = eb1[tid]; sb2[tid] = eb2[tid]; }
    if (tid < 400) sW2[tid] = eW2[tid];
    if (tid < 100) sW3[tid] = eW3[tid];
    if (tid < 5)   sb3[tid] = eb3[tid];
    cand[tid] = INFINITY;
    if (tid == 0) s_n = 0;
    __syncthreads();

    // ---- phase 1: layer-1 breakpoints via warp rank-sort ----
    if (tid < 32) {
        float tj = INFINITY;
        if (tid < 20) {
            float a = sa[tid];
            if (a != 0.0f) {
                float t = -sb1[tid] / a;
                if (isfinite(t)) tj = t;
            }
        }
        int rnk = 0;
        #pragma unroll
        for (int j = 0; j < 32; j++) {
            float u = __shfl_sync(0xFFFFFFFFu, tj, j);
            rnk += (u < tj) || (u == tj && j < tid);
        }
        bool fin = isfinite(tj);
        if (fin) { s_t[rnk] = tj; cand[rnk] = tj; }
        unsigned m = __ballot_sync(0xFFFFFFFFu, fin);
        if (tid == 0) { s_n1 = __popc(m); atomicAdd(&s_n, __popc(m)); }
    }
    __syncthreads();
    const int n1 = s_n1;

    // ---- phase 2: layer-2 zero crossings ----
    if (tid < 21 * 20) {
        int p = tid / 20, k = tid % 20;
        if (p <= n1) {
            float lo = (p == 0)  ? -INFINITY : s_t[p - 1];
            float hi = (p == n1) ?  INFINITY : s_t[p];
            float xr;
            if (n1 == 0)      xr = 0.0f;
            else if (p == 0)  xr = s_t[0] - 1.0f;
            else if (p == n1) xr = s_t[n1 - 1] + 1.0f;
            else              xr = 0.5f * (lo + hi);
            float zs = 0.0f, zi = sb2[k];
            for (int j = 0; j < 20; j++) {
                float pre = fmaf(sa[j], xr, sb1[j]);
                if (pre > 0.0f) {
                    zs = fmaf(sa[j],  sW2[j * 20 + k], zs);
                    zi = fmaf(sb1[j], sW2[j * 20 + k], zi);
                }
            }
            if (zs != 0.0f) {
                float xc = -zi / zs;
                if (isfinite(xc) && xc > lo && xc < hi) {
                    cand[20 + p * 20 + k] = xc;
                    atomicAdd(&s_n, 1);
                }
            }
        }
    }
    __syncthreads();

    // ---- phase 3: hybrid bitonic sort ----
    {
        float v = cand[tid];
        for (int k = 2; k <= 512; k <<= 1) {
            for (int j = k >> 1; j > 0; j >>= 1) {
                float u;
                if (j >= 32) {
                    cand[tid] = v; __syncthreads();
                    u = cand[tid ^ j]; __syncthreads();
                } else {
                    u = __shfl_xor_sync(0xFFFFFFFFu, v, j);
                }
                bool up = ((tid & k) == 0);
                bool keepmin = (up == ((tid & j) == 0));
                v = keepmin ? fminf(v, u) : fmaxf(v, u);
            }
        }
        cand[tid] = v;
        __syncthreads();
    }
    const int n = s_n;

    // ---- phase 4: per-segment affine coefficients (threads 0..n) ----
    if (tid <= n) {
        float xr;
        if (n == 0)        xr = 0.0f;
        else if (tid == 0) xr = cand[0] - 1.0f;
        else if (tid == n) xr = cand[n - 1] + 1.0f;
        else               xr = 0.5f * (cand[tid - 1] + cand[tid]);

        float ha[20], hb[20];
        #pragma unroll
        for (int j = 0; j < 20; j++) {
            float pre = fmaf(sa[j], xr, sb1[j]);
            bool act = pre > 0.0f;
            ha[j] = act ? sa[j]  : 0.0f;
            hb[j] = act ? sb1[j] : 0.0f;
        }
        float sm[5] = {0, 0, 0, 0, 0}, cm[5] = {0, 0, 0, 0, 0};
        #pragma unroll 2
        for (int k = 0; k < 20; k++) {
            float zs = 0.0f, zi = sb2[k];
            #pragma unroll
            for (int j = 0; j < 20; j++) {
                zs = fmaf(ha[j], sW2[j * 20 + k], zs);
                zi = fmaf(hb[j], sW2[j * 20 + k], zi);
            }
            if (fmaf(zs, xr, zi) > 0.0f) {
                #pragma unroll
                for (int m = 0; m < 5; m++) {
                    sm[m] = fmaf(zs, sW3[k * 5 + m], sm[m]);
                    cm[m] = fmaf(zi, sW3[k * 5 + m], cm[m]);
                }
            }
        }
        #pragma unroll
        for (int m = 0; m < 5; m++) {
            seg_s[tid * 5 + m] = sm[m];
            seg_c[tid * 5 + m] = cm[m] + sb3[m];
        }
    }
    __syncthreads();

    // ---- phase 5: per-cell table (2 cells/thread) ----
    for (int c = tid; c < NG; c += 512) {
        float center = XLO_F + ((float)c + 0.5f) * STEP_F;
        int lo = 0, hi = n;
        while (lo < hi) {
            int mid = (lo + hi) >> 1;
            if (cand[mid] <= center) lo = mid + 1; else hi = mid;
        }
        const int s = lo;                        // segment containing center
        unsigned p[5];
        #pragma unroll
        for (int m = 0; m < 5; m++) {
            float sl = seg_s[s * 5 + m];
            float v  = fmaf(sl, center, seg_c[s * 5 + m]);
            __half2 h = __floats2half2_rn(sl * 0.015625f, v * 0.015625f);
            p[m] = *(unsigned*)&h;
        }
        g_AB[c] = make_uint2(p[0], p[1]);
        g_CD[c] = make_uint2(p[2], p[3]);
        g_M4[c] = p[4];
    }

    // ---- PDL: make table visible, then let the fused kernel proceed ----
    __syncthreads();
    __threadfence();
    GRIDDEP_LAUNCH();
}

// ----------------------------------------------------------------------------
// Fused encoder+decoder: thread-pair per row.
// ----------------------------------------------------------------------------
__device__ __forceinline__ void pwl_eval(float x,
                                         const uint2* __restrict__ sAB,
                                         const uint2* __restrict__ sCD,
                                         const unsigned* __restrict__ sM4,
                                         float acc[5])
{
    float u = fmaf(x, INVSTEP_F, UOFF_F);
    int c = __float2int_rz(u);
    c = min(max(c, 0), NG - 1);
    float dx = x - fmaf((float)c + 0.5f, STEP_F, XLO_F);
    uint2    ab = sAB[c];
    uint2    cd = sCD[c];
    unsigned e  = sM4[c];
    float2 m0 = __half22float2(*(__half2*)&ab.x);
    float2 m1 = __half22float2(*(__half2*)&ab.y);
    float2 m2 = __half22float2(*(__half2*)&cd.x);
    float2 m3 = __half22float2(*(__half2*)&cd.y);
    float2 m4 = __half22float2(*(__half2*)&e);
    acc[0] += fmaf(m0.x, dx, m0.y);
    acc[1] += fmaf(m1.x, dx, m1.y);
    acc[2] += fmaf(m2.x, dx, m2.y);
    acc[3] += fmaf(m3.x, dx, m3.y);
    acc[4] += fmaf(m4.x, dx, m4.y);
}

__global__ __launch_bounds__(256, 5) void fused_kernel(
    const float* __restrict__ inv,  const float* __restrict__ noninv,
    const float* __restrict__ dW1,  const float* __restrict__ db1,
    const float* __restrict__ dW2,  const float* __restrict__ db2,
    const float* __restrict__ dW3,  const float* __restrict__ db3,
    float* __restrict__ out)
{
    __shared__ __align__(16) uint2        s_AB[NG];   // 8 KB
    __shared__ __align__(16) uint2        s_CD[NG];   // 8 KB
    __shared__ __align__(16) unsigned int s_M4[NG];   // 4 KB
    __shared__ __align__(16) float        s_dw[784];  // 3.1 KB

    const int tid = threadIdx.x;

    // ---- prep-independent prologue (overlaps with prep via PDL) ----
    for (int i = tid; i < 260; i += 256) s_dw[i] = dW1[i];
    if (tid < 20) s_dw[260 + tid] = db1[tid];
    for (int i = tid; i < 400; i += 256) s_dw[280 + i] = dW2[i];
    if (tid < 20) s_dw[680 + tid] = db2[tid];
    if (tid < 80) s_dw[700 + tid] = dW3[tid];
    if (tid < 4)  s_dw[780 + tid] = db3[tid];

    // ---- wait for prep's table, then copy it in ----
    GRIDDEP_WAIT();
    {
        const uint4* a = (const uint4*)g_AB;             // 512 uint4
        const uint4* b = (const uint4*)g_CD;             // 512 uint4
        const uint4* m = (const uint4*)g_M4;             // 256 uint4
        uint4* da = (uint4*)s_AB;
        uint4* db = (uint4*)s_CD;
        uint4* dm = (uint4*)s_M4;
        #pragma unroll
        for (int i = tid; i < NG / 2; i += 256) { da[i] = a[i]; db[i] = b[i]; }
        if (tid < NG / 4) dm[tid] = m[tid];
    }
    __syncthreads();

    const int gtid = blockIdx.x * 256 + tid;
    const int r    = gtid >> 1;          // row
    const int half = gtid & 1;           // 0/1: input half + neuron half
    const int nb   = half * 10;          // neuron base

    // -------- encoder: my 32 of the row's 64 inputs --------
    float acc[5] = {0, 0, 0, 0, 0};
    const float4* p0 = (const float4*)inv + (size_t)r * 16 + half * 8;
    #pragma unroll
    for (int i = 0; i < 8; i++) {
        float4 a = p0[i];
        pwl_eval(a.x, s_AB, s_CD, s_M4, acc);
        pwl_eval(a.y, s_AB, s_CD, s_M4, acc);
        pwl_eval(a.z, s_AB, s_CD, s_M4, acc);
        pwl_eval(a.w, s_AB, s_CD, s_M4, acc);
    }

    // -------- combine moments across the pair; build cat[13] --------
    float cat[13];
    #pragma unroll
    for (int m = 0; m < 5; m++)
        cat[m] = acc[m] + __shfl_xor_sync(0xFFFFFFFFu, acc[m], 1);
    {
        float4 u0 = *(const float4*)(noninv + (size_t)r * 8);
        float4 u1 = *(const float4*)(noninv + (size_t)r * 8 + 4);
        cat[5] = u0.x; cat[6] = u0.y; cat[7]  = u0.z; cat[8]  = u0.w;
        cat[9] = u1.x; cat[10] = u1.y; cat[11] = u1.z; cat[12] = u1.w;
    }

    // -------- decoder layer 1: my 10 neurons --------
    float myh[10];
    #pragma unroll
    for (int i = 0; i < 10; i += 2) {
        float2 z = *(const float2*)&s_dw[260 + nb + i];
        #pragma unroll
        for (int c = 0; c < 13; c++) {
            float2 w = *(const float2*)&s_dw[c * 20 + nb + i];
            z.x = fmaf(cat[c], w.x, z.x);
            z.y = fmaf(cat[c], w.y, z.y);
        }
        myh[i]     = fmaxf(z.x, 0.0f);
        myh[i + 1] = fmaxf(z.y, 0.0f);
    }

    // -------- exchange h halves --------
    float hall[20];
    #pragma unroll
    for (int i = 0; i < 10; i++) {
        float o = __shfl_xor_sync(0xFFFFFFFFu, myh[i], 1);
        hall[i]      = half ? o      : myh[i];
        hall[10 + i] = half ? myh[i] : o;
    }

    // -------- decoder layer 2: my 10 neurons --------
    float g[10];
    #pragma unroll
    for (int i = 0; i < 10; i += 2) {
        float2 z = *(const float2*)&s_dw[680 + nb + i];
        #pragma unroll
        for (int j = 0; j < 20; j++) {
            float2 w = *(const float2*)&s_dw[280 + j * 20 + nb + i];
            z.x = fmaf(hall[j], w.x, z.x);
            z.y = fmaf(hall[j], w.y, z.y);
        }
        g[i]     = fmaxf(z.x, 0.0f);
        g[i + 1] = fmaxf(z.y, 0.0f);
    }

    // -------- decoder layer 3: partial + shfl reduce --------
    float4 o = half ? make_float4(0.f, 0.f, 0.f, 0.f)
                    : *(const float4*)&s_dw[780];
    #pragma unroll
    for (int i = 0; i < 10; i++) {
        float4 w = *(const float4*)&s_dw[700 + (nb + i) * 4];
        o.x = fmaf(g[i], w.x, o.x);
        o.y = fmaf(g[i], w.y, o.y);
        o.z = fmaf(g[i], w.z, o.z);
        o.w = fmaf(g[i], w.w, o.w);
    }
    o.x += __shfl_xor_sync(0xFFFFFFFFu, o.x, 1);
    o.y += __shfl_xor_sync(0xFFFFFFFFu, o.y, 1);
    o.z += __shfl_xor_sync(0xFFFFFFFFu, o.z, 1);
    o.w += __shfl_xor_sync(0xFFFFFFFFu, o.w, 1);
    if (half == 0)
        *(float4*)(out + (size_t)r * 4) = o;
}

// ----------------------------------------------------------------------------
extern "C" void kernel_launch(void* const* d_in, const int* in_sizes, int n_in,
                              void* d_out, int out_size)
{
    (void)in_sizes; (void)n_in; (void)out_size;
    const float* invar  = (const float*)d_in[0];
    const float* noninv = (const float*)d_in[1];
    const float* eW1 = (const float*)d_in[2];
    const float* eb1 = (const float*)d_in[3];
    const float* eW2 = (const float*)d_in[4];
    const float* eb2 = (const float*)d_in[5];
    const float* eW3 = (const float*)d_in[6];
    const float* eb3 = (const float*)d_in[7];
    const float* dW1 = (const float*)d_in[8];
    const float* db1 = (const float*)d_in[9];
    const float* dW2 = (const float*)d_in[10];
    const float* db2 = (const float*)d_in[11];
    const float* dW3 = (const float*)d_in[12];
    const float* db3 = (const float*)d_in[13];

    prep_kernel<<<1, 512>>>(eW1, eb1, eW2, eb2, eW3, eb3);

    // fused launch with programmatic dependent launch (overlaps prep tail)
    cudaLaunchConfig_t cfg = {};
    cfg.gridDim  = dim3(BATCH / 128, 1, 1);
    cfg.blockDim = dim3(256, 1, 1);
    cfg.dynamicSmemBytes = 0;
    cfg.stream = 0;
    cudaLaunchAttribute attrs[1];
    attrs[0].id = cudaLaunchAttributeProgrammaticStreamSerialization;
    attrs[0].val.programmaticStreamSerializationAllowed = 1;
    cfg.attrs = attrs;
    cfg.numAttrs = 1;
    cudaLaunchKernelEx(&cfg, fused_kernel,
                       invar, noninv, dW1, db1, dW2, db2, dW3, db3,
                       (float*)d_out);
}